// round 1
// baseline (speedup 1.0000x reference)
#include <cuda_runtime.h>
#include <math.h>

#define NMAX 50000
#define EMAX 800000
#define ETOT (EMAX + NMAX)

// ---------------- device scratch (static: no allocations allowed) ----------
__device__ int   g_deg[NMAX];
__device__ int   g_rowptr[NMAX + 1];
__device__ int   g_cursor[NMAX];
__device__ int   g_csrc[ETOT];
__device__ float g_score[(size_t)ETOT * 4];
__device__ float g_xl[(size_t)NMAX * 256];
__device__ float g_xr[(size_t)NMAX * 256];
__device__ float g_h [(size_t)NMAX * 256];

// ---------------- CSR build (counting sort by dst) -------------------------
__global__ void k_init_deg(int n) {
    int i = blockIdx.x * blockDim.x + threadIdx.x;
    if (i < n) g_deg[i] = 1;               // self-loop contributes 1
}

__global__ void k_count(const int* __restrict__ dst, int E) {
    int e = blockIdx.x * blockDim.x + threadIdx.x;
    if (e < E) atomicAdd(&g_deg[dst[e]], 1);
}

__global__ void k_scan(int n) {
    __shared__ int sh[1024];
    int t = threadIdx.x;
    int Cn = (n + 1023) >> 10;
    int beg = t * Cn;
    int end = min(beg + Cn, n);
    int s = 0;
    for (int i = beg; i < end; i++) s += g_deg[i];
    sh[t] = s;
    __syncthreads();
    for (int o = 1; o < 1024; o <<= 1) {
        int v = (t >= o) ? sh[t - o] : 0;
        __syncthreads();
        sh[t] += v;
        __syncthreads();
    }
    int run = sh[t] - s;                   // exclusive prefix for this thread
    for (int i = beg; i < end; i++) {
        g_rowptr[i] = run;
        g_cursor[i] = run;
        run += g_deg[i];
    }
    if (end == n && beg < n) g_rowptr[n] = run;
}

__global__ void k_scatter(const int* __restrict__ src, const int* __restrict__ dst,
                          int E, int n) {
    int i = blockIdx.x * blockDim.x + threadIdx.x;
    if (i < E) {
        int d = dst[i];
        int p = atomicAdd(&g_cursor[d], 1);
        g_csrc[p] = src[i];
    } else if (i < E + n) {
        int v = i - E;                      // self loop
        int p = atomicAdd(&g_cursor[v], 1);
        g_csrc[p] = v;
    }
}

// ---------------- layer-0 projection (x is N x 1: outer product) -----------
__global__ void k_proj0(const float* __restrict__ x,
                        const float* __restrict__ Wl, const float* __restrict__ bl,
                        const float* __restrict__ Wr, const float* __restrict__ br,
                        float* __restrict__ xl, float* __restrict__ xr, int n) {
    int idx = blockIdx.x * blockDim.x + threadIdx.x;
    if (idx >= n * 256) return;
    int f = idx & 255;
    int i = idx >> 8;
    float xv = x[i];
    xl[idx] = fmaf(xv, Wl[f], bl[f]);
    xr[idx] = fmaf(xv, Wr[f], br[f]);
}

// ---------------- generic SGEMM + bias (A:MxK row-major, B:KxN row-major) --
__global__ void sgemm_bias(const float* __restrict__ A, const float* __restrict__ B,
                           const float* __restrict__ bias, float* __restrict__ C,
                           int M, int N, int K) {
    __shared__ float As[16][65];
    __shared__ float Bs[16][65];
    int bm = blockIdx.x * 64, bn = blockIdx.y * 64;
    int tid = threadIdx.x;
    int tx = tid & 15, ty = tid >> 4;
    float acc[4][4] = {};
    for (int k0 = 0; k0 < K; k0 += 16) {
#pragma unroll
        for (int l = 0; l < 4; l++) {
            int lin = tid + l * 256;
            int kk = lin & 15, mm = lin >> 4;
            int gm = bm + mm;
            As[kk][mm] = (gm < M) ? A[(size_t)gm * K + k0 + kk] : 0.f;
        }
#pragma unroll
        for (int l = 0; l < 4; l++) {
            int lin = tid + l * 256;
            int nn = lin & 63, kk = lin >> 6;
            Bs[kk][nn] = B[(size_t)(k0 + kk) * N + bn + nn];
        }
        __syncthreads();
#pragma unroll
        for (int kk = 0; kk < 16; kk++) {
            float a[4], b[4];
#pragma unroll
            for (int i = 0; i < 4; i++) a[i] = As[kk][ty * 4 + i];
#pragma unroll
            for (int j = 0; j < 4; j++) b[j] = Bs[kk][tx * 4 + j];
#pragma unroll
            for (int i = 0; i < 4; i++)
#pragma unroll
                for (int j = 0; j < 4; j++)
                    acc[i][j] = fmaf(a[i], b[j], acc[i][j]);
        }
        __syncthreads();
    }
#pragma unroll
    for (int i = 0; i < 4; i++) {
        int gm = bm + ty * 4 + i;
        if (gm < M) {
#pragma unroll
            for (int j = 0; j < 4; j++) {
                int gn = bn + tx * 4 + j;
                C[(size_t)gm * N + gn] = acc[i][j] + bias[gn];
            }
        }
    }
}

// ---------------- vector load helper ---------------------------------------
template<int FPL>
__device__ __forceinline__ void ldv(const float* __restrict__ p, float* v) {
    if constexpr (FPL == 8) {
        float4 a = *(const float4*)p;
        float4 b = *(const float4*)(p + 4);
        v[0] = a.x; v[1] = a.y; v[2] = a.z; v[3] = a.w;
        v[4] = b.x; v[5] = b.y; v[6] = b.z; v[7] = b.w;
    } else if constexpr (FPL == 2) {
        float2 a = *(const float2*)p;
        v[0] = a.x; v[1] = a.y;
    } else {
#pragma unroll
        for (int j = 0; j < FPL; j++) v[j] = p[j];
    }
}

// ---------------- fused GATv2 attention + aggregate + bias + LN + ELU ------
// One warp per destination node. Edges CSR-sorted by dst.
template<int H, int C>
__global__ void k_gat(const float* __restrict__ xl, const float* __restrict__ xr,
                      const float* __restrict__ att, const float* __restrict__ bias,
                      const float* __restrict__ gamma, const float* __restrict__ beta,
                      float* __restrict__ hout, int n) {
    constexpr int F = H * C;        // features
    constexpr int FPL = F / 32;     // features per lane
    constexpr int GROUP = C / FPL;  // lanes per head
    int w = (blockIdx.x * blockDim.x + threadIdx.x) >> 5;
    int lane = threadIdx.x & 31;
    if (w >= n) return;
    const int d = w;
    const int fb = lane * FPL;
    const int h = lane / GROUP;

    float xrv[FPL], attv[FPL];
    ldv<FPL>(xr + (size_t)d * F + fb, xrv);
    ldv<FPL>(att + fb, attv);

    int beg = g_rowptr[d], end = g_rowptr[d + 1];

    // pass 1: scores + per-head max
    float hmax = -3.0e38f;
    for (int e = beg; e < end; e++) {
        int s = g_csrc[e];
        float v[FPL];
        ldv<FPL>(xl + (size_t)s * F + fb, v);
        float p = 0.f;
#pragma unroll
        for (int j = 0; j < FPL; j++) {
            float t = v[j] + xrv[j];
            t = (t > 0.f) ? t : 0.2f * t;     // leaky_relu 0.2
            p = fmaf(t, attv[j], p);
        }
#pragma unroll
        for (int o = 1; o < GROUP; o <<= 1) p += __shfl_xor_sync(0xffffffffu, p, o);
        if ((lane & (GROUP - 1)) == 0) g_score[(size_t)e * H + h] = p;
        hmax = fmaxf(hmax, p);
    }

    // pass 2: exp + per-head sum (overwrite score with exp)
    float hsum = 0.f;
    for (int e = beg; e < end; e++) {
        float ex = expf(g_score[(size_t)e * H + h] - hmax);
        if ((lane & (GROUP - 1)) == 0) g_score[(size_t)e * H + h] = ex;
        hsum += ex;
    }
    float inv = 1.f / (hsum + 1e-16f);

    // pass 3: weighted aggregate
    float acc[FPL];
#pragma unroll
    for (int j = 0; j < FPL; j++) acc[j] = 0.f;
    for (int e = beg; e < end; e++) {
        int s = g_csrc[e];
        float wgt = g_score[(size_t)e * H + h] * inv;
        float v[FPL];
        ldv<FPL>(xl + (size_t)s * F + fb, v);
#pragma unroll
        for (int j = 0; j < FPL; j++) acc[j] = fmaf(wgt, v[j], acc[j]);
    }

    // bias
#pragma unroll
    for (int j = 0; j < FPL; j++) acc[j] += bias[fb + j];

    // LayerNorm over F across the warp
    float m = 0.f;
#pragma unroll
    for (int j = 0; j < FPL; j++) m += acc[j];
#pragma unroll
    for (int o = 16; o >= 1; o >>= 1) m += __shfl_xor_sync(0xffffffffu, m, o);
    m *= (1.f / F);
    float var = 0.f;
#pragma unroll
    for (int j = 0; j < FPL; j++) { float dq = acc[j] - m; var = fmaf(dq, dq, var); }
#pragma unroll
    for (int o = 16; o >= 1; o >>= 1) var += __shfl_xor_sync(0xffffffffu, var, o);
    var *= (1.f / F);
    float rs = rsqrtf(var + 1e-5f);

    // scale/shift + ELU
#pragma unroll
    for (int j = 0; j < FPL; j++) {
        float y = fmaf((acc[j] - m) * rs, gamma[fb + j], beta[fb + j]);
        y = (y > 0.f) ? y : expm1f(y);
        hout[(size_t)d * F + fb + j] = y;
    }
}

// ---------------- MLP head on node 0 ---------------------------------------
__global__ void k_head(const float* __restrict__ h,
                       const float* __restrict__ rw1, const float* __restrict__ rb1,
                       const float* __restrict__ rw2, const float* __restrict__ rb2,
                       float* __restrict__ out) {
    int t = threadIdx.x;  // 32 threads, t = hidden unit
    float s = rb1[t];
    for (int i = 0; i < 64; i++) s = fmaf(h[i], rw1[i * 32 + t], s);
    float z = 0.5f * s * (1.f + erff(s * 0.70710678118654752f)); // exact gelu
    float val = z * rw2[t];
#pragma unroll
    for (int o = 16; o >= 1; o >>= 1) val += __shfl_xor_sync(0xffffffffu, val, o);
    if (t == 0) out[0] = val + rb2[0];
}

// ---------------- launch ----------------------------------------------------
extern "C" void kernel_launch(void* const* d_in, const int* in_sizes, int n_in,
                              void* d_out, int out_size) {
    const float* x    = (const float*)d_in[0];
    const int*   ei   = (const int*)  d_in[1];
    const float* Wl0  = (const float*)d_in[2];
    const float* bl0  = (const float*)d_in[3];
    const float* Wr0  = (const float*)d_in[4];
    const float* br0  = (const float*)d_in[5];
    const float* att0 = (const float*)d_in[6];
    const float* bias0= (const float*)d_in[7];
    const float* Wl1  = (const float*)d_in[8];
    const float* bl1  = (const float*)d_in[9];
    const float* Wr1  = (const float*)d_in[10];
    const float* br1  = (const float*)d_in[11];
    const float* att1 = (const float*)d_in[12];
    const float* bias1= (const float*)d_in[13];
    const float* Wl2  = (const float*)d_in[14];
    const float* bl2  = (const float*)d_in[15];
    const float* Wr2  = (const float*)d_in[16];
    const float* br2  = (const float*)d_in[17];
    const float* att2 = (const float*)d_in[18];
    const float* bias2= (const float*)d_in[19];
    const float* g0   = (const float*)d_in[20];
    const float* be0  = (const float*)d_in[21];
    const float* g1   = (const float*)d_in[22];
    const float* be1  = (const float*)d_in[23];
    const float* g2   = (const float*)d_in[24];
    const float* be2  = (const float*)d_in[25];
    const float* rw1  = (const float*)d_in[26];
    const float* rb1  = (const float*)d_in[27];
    const float* rw2  = (const float*)d_in[28];
    const float* rb2  = (const float*)d_in[29];
    float* out = (float*)d_out;

    int n = in_sizes[0];           // 50000 (x is N x 1)
    int E = in_sizes[1] / 2;       // 800000
    const int* src = ei;
    const int* dst = ei + E;

    float *p_xl, *p_xr, *p_h;
    cudaGetSymbolAddress((void**)&p_xl, g_xl);
    cudaGetSymbolAddress((void**)&p_xr, g_xr);
    cudaGetSymbolAddress((void**)&p_h,  g_h);

    // CSR build (dst-sorted)
    k_init_deg<<<(n + 255) / 256, 256>>>(n);
    k_count<<<(E + 255) / 256, 256>>>(dst, E);
    k_scan<<<1, 1024>>>(n);
    k_scatter<<<(E + n + 255) / 256, 256>>>(src, dst, E, n);

    int gatBlocks = (n * 32 + 255) / 256;

    // Layer 0: rank-1 projections, H=4, C=64
    k_proj0<<<(n * 256 + 255) / 256, 256>>>(x, Wl0, bl0, Wr0, br0, p_xl, p_xr, n);
    k_gat<4, 64><<<gatBlocks, 256>>>(p_xl, p_xr, att0, bias0, g0, be0, p_h, n);

    // Layer 1: 256x256 projections, H=4, C=64
    {
        dim3 grid((n + 63) / 64, 4);
        sgemm_bias<<<grid, 256>>>(p_h, Wl1, bl1, p_xl, n, 256, 256);
        sgemm_bias<<<grid, 256>>>(p_h, Wr1, br1, p_xr, n, 256, 256);
    }
    k_gat<4, 64><<<gatBlocks, 256>>>(p_xl, p_xr, att1, bias1, g1, be1, p_h, n);

    // Layer 2: 256x64 projections, H=1, C=64
    {
        dim3 grid((n + 63) / 64, 1);
        sgemm_bias<<<grid, 256>>>(p_h, Wl2, bl2, p_xl, n, 64, 256);
        sgemm_bias<<<grid, 256>>>(p_h, Wr2, br2, p_xr, n, 64, 256);
    }
    k_gat<1, 64><<<gatBlocks, 256>>>(p_xl, p_xr, att2, bias2, g2, be2, p_h, n);

    // Head on node 0
    k_head<<<1, 32>>>(p_h, rw1, rb1, rw2, rb2, out);
}

// round 3
// speedup vs baseline: 1.4926x; 1.4926x over previous
#include <cuda_runtime.h>
#include <math.h>

#define NMAX 50000
#define EMAX 800000
#define ETOT (EMAX + NMAX)

// ---------------- device scratch (static: no allocations allowed) ----------
__device__ int   g_deg[NMAX];
__device__ int   g_rowptr[NMAX + 1];
__device__ int   g_cursor[NMAX];
__device__ int   g_csrc[ETOT];
__device__ __align__(16) float g_xl[(size_t)NMAX * 256];
__device__ __align__(16) float g_xr[(size_t)NMAX * 256];
__device__ __align__(16) float g_h [(size_t)NMAX * 256];

// ---------------- CSR build (counting sort by dst) -------------------------
__global__ void k_init_deg(int n) {
    int i = blockIdx.x * blockDim.x + threadIdx.x;
    if (i < n) g_deg[i] = 1;               // self-loop contributes 1
}

__global__ void k_count(const int* __restrict__ dst, int E) {
    int e = blockIdx.x * blockDim.x + threadIdx.x;
    if (e < E) atomicAdd(&g_deg[dst[e]], 1);
}

__global__ void k_scan(int n) {
    __shared__ int sh[1024];
    int t = threadIdx.x;
    int Cn = (n + 1023) >> 10;
    int beg = t * Cn;
    int end = min(beg + Cn, n);
    int s = 0;
    for (int i = beg; i < end; i++) s += g_deg[i];
    sh[t] = s;
    __syncthreads();
    for (int o = 1; o < 1024; o <<= 1) {
        int v = (t >= o) ? sh[t - o] : 0;
        __syncthreads();
        sh[t] += v;
        __syncthreads();
    }
    int run = sh[t] - s;                   // exclusive prefix for this thread
    for (int i = beg; i < end; i++) {
        g_rowptr[i] = run;
        g_cursor[i] = run;
        run += g_deg[i];
    }
    if (end == n && beg < n) g_rowptr[n] = run;
}

__global__ void k_scatter(const int* __restrict__ src, const int* __restrict__ dst,
                          int E, int n) {
    int i = blockIdx.x * blockDim.x + threadIdx.x;
    if (i < E) {
        int d = dst[i];
        int p = atomicAdd(&g_cursor[d], 1);
        g_csrc[p] = src[i];
    } else if (i < E + n) {
        int v = i - E;                      // self loop
        int p = atomicAdd(&g_cursor[v], 1);
        g_csrc[p] = v;
    }
}

// ---------------- fused dual SGEMM + bias (A:MxK, B:KxN row-major) ---------
// 128 x BN block tile, 8 x TN register tile, 256 threads.
// blockIdx.y < ytiles -> (Bl,bl)->Cl ; else (Br,br)->Cr.
template<int BN, int TN>
__global__ void sgemm_dual(const float* __restrict__ A,
                           const float* __restrict__ Bl, const float* __restrict__ bll,
                           float* __restrict__ Cl,
                           const float* __restrict__ Br, const float* __restrict__ brr,
                           float* __restrict__ Cr,
                           int M, int N, int K, int ytiles) {
    constexpr int BM = 128, BK = 16, TM = 8;
    constexpr int TX = BN / TN;             // threads along n
    const float* B; const float* bias; float* C;
    int by = blockIdx.y;
    if (by < ytiles) { B = Bl; bias = bll; C = Cl; }
    else             { B = Br; bias = brr; C = Cr; by -= ytiles; }
    int bm = blockIdx.x * BM, bn = by * BN;

    __shared__ float As[BK][BM + 4];
    __shared__ float Bs[BK][BN + 4];

    int tid = threadIdx.x;
    int tx = tid % TX, ty = tid / TX;       // ty in [0,16)
    float acc[TM][TN] = {};

    for (int k0 = 0; k0 < K; k0 += BK) {
        // A tile: 128x16 = 512 float4, 2 per thread (transposed into As)
#pragma unroll
        for (int i = 0; i < 2; i++) {
            int l = tid + i * 256;
            int row = l >> 2, c4 = (l & 3) * 4;
            int gm = bm + row;
            float4 v = make_float4(0.f, 0.f, 0.f, 0.f);
            if (gm < M) v = *(const float4*)(A + (size_t)gm * K + k0 + c4);
            As[c4 + 0][row] = v.x; As[c4 + 1][row] = v.y;
            As[c4 + 2][row] = v.z; As[c4 + 3][row] = v.w;
        }
        // B tile: 16 x BN
        constexpr int BF4 = BK * BN / 4;
#pragma unroll
        for (int i = 0; i < BF4 / 256; i++) {
            int l = tid + i * 256;
            int row = l / (BN / 4), c4 = (l % (BN / 4)) * 4;
            float4 v = *(const float4*)(B + (size_t)(k0 + row) * N + bn + c4);
            *(float4*)&Bs[row][c4] = v;
        }
        __syncthreads();
#pragma unroll
        for (int kk = 0; kk < BK; kk++) {
            float a[TM], b[TN];
            *(float4*)&a[0] = *(const float4*)&As[kk][ty * TM];
            *(float4*)&a[4] = *(const float4*)&As[kk][ty * TM + 4];
            *(float4*)&b[0] = *(const float4*)&Bs[kk][tx * TN];
            if constexpr (TN == 8)
                *(float4*)&b[4] = *(const float4*)&Bs[kk][tx * TN + 4];
#pragma unroll
            for (int i = 0; i < TM; i++)
#pragma unroll
                for (int j = 0; j < TN; j++)
                    acc[i][j] = fmaf(a[i], b[j], acc[i][j]);
        }
        __syncthreads();
    }

#pragma unroll
    for (int i = 0; i < TM; i++) {
        int gm = bm + ty * TM + i;
        if (gm < M) {
#pragma unroll
            for (int j4 = 0; j4 < TN; j4 += 4) {
                int gn = bn + tx * TN + j4;
                float4 o;
                o.x = acc[i][j4 + 0] + bias[gn + 0];
                o.y = acc[i][j4 + 1] + bias[gn + 1];
                o.z = acc[i][j4 + 2] + bias[gn + 2];
                o.w = acc[i][j4 + 3] + bias[gn + 3];
                *(float4*)(C + (size_t)gm * N + gn) = o;
            }
        }
    }
}

// ---------------- layer-0 GAT (rank-1 input): scalar online softmax --------
// x is N x 1 so xl[s] = x[s]*Wl + bl. Softmax weights sum to 1, so
// out = Wl * (sum_e a_e x[s_e]) + bl. One warp per node; H=4, C=64.
__global__ void k_gat0(const float* __restrict__ x,
                       const float* __restrict__ Wl, const float* __restrict__ bl,
                       const float* __restrict__ Wr, const float* __restrict__ br,
                       const float* __restrict__ att, const float* __restrict__ bias,
                       const float* __restrict__ gamma, const float* __restrict__ beta,
                       float* __restrict__ hout, int n) {
    int w = (blockIdx.x * blockDim.x + threadIdx.x) >> 5;
    int lane = threadIdx.x & 31;
    if (w >= n) return;
    const int d = w;
    const int fb = lane * 8;

    float wl[8], blv[8], attv[8], Cv[8];
    float xd = x[d];
#pragma unroll
    for (int j = 0; j < 8; j++) {
        wl[j]   = Wl[fb + j];
        blv[j]  = bl[fb + j];
        Cv[j]   = blv[j] + fmaf(xd, Wr[fb + j], br[fb + j]);
        attv[j] = att[fb + j];
    }

    int beg = g_rowptr[d], end = g_rowptr[d + 1];
    float m = -3.0e38f, ssum = 0.f, accx = 0.f;
    for (int e = beg; e < end; e++) {
        int s = g_csrc[e];
        float xs = x[s];
        float p = 0.f;
#pragma unroll
        for (int j = 0; j < 8; j++) {
            float t = fmaf(xs, wl[j], Cv[j]);
            t = (t > 0.f) ? t : 0.2f * t;          // leaky_relu 0.2
            p = fmaf(t, attv[j], p);
        }
        p += __shfl_xor_sync(0xffffffffu, p, 1);   // reduce within head (8 lanes)
        p += __shfl_xor_sync(0xffffffffu, p, 2);
        p += __shfl_xor_sync(0xffffffffu, p, 4);
        if (p <= m) {                               // running max unchanged
            float ww = __expf(p - m);
            ssum += ww;
            accx = fmaf(ww, xs, accx);
        } else {                                    // rescale old state
            float sc = __expf(m - p);
            ssum = fmaf(ssum, sc, 1.f);
            accx = fmaf(accx, sc, xs);
            m = p;
        }
    }
    float inv = 1.f / (ssum + 1e-16f);
    accx *= inv;

    // out_j = accx * Wl_j + bl_j  (+ layer bias), then LN + ELU
    float v8[8];
    float mean = 0.f;
#pragma unroll
    for (int j = 0; j < 8; j++) {
        float y = fmaf(accx, wl[j], blv[j]) + bias[fb + j];
        v8[j] = y;
        mean += y;
    }
#pragma unroll
    for (int o = 16; o >= 1; o >>= 1) mean += __shfl_xor_sync(0xffffffffu, mean, o);
    mean *= (1.f / 256.f);
    float var = 0.f;
#pragma unroll
    for (int j = 0; j < 8; j++) { float dq = v8[j] - mean; var = fmaf(dq, dq, var); }
#pragma unroll
    for (int o = 16; o >= 1; o >>= 1) var += __shfl_xor_sync(0xffffffffu, var, o);
    var *= (1.f / 256.f);
    float rs = rsqrtf(var + 1e-5f);
    float out[8];
#pragma unroll
    for (int j = 0; j < 8; j++) {
        float y = fmaf((v8[j] - mean) * rs, gamma[fb + j], beta[fb + j]);
        out[j] = (y > 0.f) ? y : expm1f(y);        // ELU
    }
    float* op = hout + (size_t)d * 256 + fb;
    *(float4*)op       = make_float4(out[0], out[1], out[2], out[3]);
    *(float4*)(op + 4) = make_float4(out[4], out[5], out[6], out[7]);
}

// ---------------- gather-GAT (layers 1-2): single-pass online softmax ------
// One warp per destination node; edges CSR-sorted by dst.
template<int H, int C>
__global__ void k_gatG(const float* __restrict__ xl, const float* __restrict__ xr,
                       const float* __restrict__ att, const float* __restrict__ bias,
                       const float* __restrict__ gamma, const float* __restrict__ beta,
                       float* __restrict__ hout, int n) {
    constexpr int F = H * C;        // features
    constexpr int FPL = F / 32;     // features per lane (8 or 2)
    constexpr int GROUP = C / FPL;  // lanes per head
    int w = (blockIdx.x * blockDim.x + threadIdx.x) >> 5;
    int lane = threadIdx.x & 31;
    if (w >= n) return;
    const int d = w;
    const int fb = lane * FPL;

    float xrv[FPL], attv[FPL];
    if constexpr (FPL == 8) {
        *(float4*)&xrv[0]  = *(const float4*)(xr + (size_t)d * F + fb);
        *(float4*)&xrv[4]  = *(const float4*)(xr + (size_t)d * F + fb + 4);
        *(float4*)&attv[0] = *(const float4*)(att + fb);
        *(float4*)&attv[4] = *(const float4*)(att + fb + 4);
    } else {
        *(float2*)&xrv[0]  = *(const float2*)(xr + (size_t)d * F + fb);
        *(float2*)&attv[0] = *(const float2*)(att + fb);
    }

    int beg = g_rowptr[d], end = g_rowptr[d + 1];
    float m = -3.0e38f, ssum = 0.f;
    float acc[FPL];
#pragma unroll
    for (int j = 0; j < FPL; j++) acc[j] = 0.f;

    for (int e = beg; e < end; e++) {
        int s = g_csrc[e];
        float v[FPL];
        const float* vp = xl + (size_t)s * F + fb;
        if constexpr (FPL == 8) {
            *(float4*)&v[0] = *(const float4*)vp;
            *(float4*)&v[4] = *(const float4*)(vp + 4);
        } else {
            *(float2*)&v[0] = *(const float2*)vp;
        }
        float p = 0.f;
#pragma unroll
        for (int j = 0; j < FPL; j++) {
            float t = v[j] + xrv[j];
            t = (t > 0.f) ? t : 0.2f * t;          // leaky_relu 0.2
            p = fmaf(t, attv[j], p);
        }
#pragma unroll
        for (int o = 1; o < GROUP; o <<= 1) p += __shfl_xor_sync(0xffffffffu, p, o);
        if (p <= m) {
            float ww = __expf(p - m);
            ssum += ww;
#pragma unroll
            for (int j = 0; j < FPL; j++) acc[j] = fmaf(ww, v[j], acc[j]);
        } else {
            float sc = __expf(m - p);
            ssum = fmaf(ssum, sc, 1.f);
#pragma unroll
            for (int j = 0; j < FPL; j++) acc[j] = fmaf(acc[j], sc, v[j]);
            m = p;
        }
    }
    float inv = 1.f / (ssum + 1e-16f);

    float mean = 0.f;
#pragma unroll
    for (int j = 0; j < FPL; j++) {
        acc[j] = fmaf(acc[j], inv, bias[fb + j]);
        mean += acc[j];
    }
#pragma unroll
    for (int o = 16; o >= 1; o >>= 1) mean += __shfl_xor_sync(0xffffffffu, mean, o);
    mean *= (1.f / F);
    float var = 0.f;
#pragma unroll
    for (int j = 0; j < FPL; j++) { float dq = acc[j] - mean; var = fmaf(dq, dq, var); }
#pragma unroll
    for (int o = 16; o >= 1; o >>= 1) var += __shfl_xor_sync(0xffffffffu, var, o);
    var *= (1.f / F);
    float rs = rsqrtf(var + 1e-5f);

    float out[FPL];
#pragma unroll
    for (int j = 0; j < FPL; j++) {
        float y = fmaf((acc[j] - mean) * rs, gamma[fb + j], beta[fb + j]);
        out[j] = (y > 0.f) ? y : expm1f(y);        // ELU
    }
    float* op = hout + (size_t)d * F + fb;
    if constexpr (FPL == 8) {
        *(float4*)op       = make_float4(out[0], out[1], out[2], out[3]);
        *(float4*)(op + 4) = make_float4(out[4], out[5], out[6], out[7]);
    } else {
        *(float2*)op = make_float2(out[0], out[1]);
    }
}

// ---------------- MLP head on node 0 ---------------------------------------
__global__ void k_head(const float* __restrict__ h,
                       const float* __restrict__ rw1, const float* __restrict__ rb1,
                       const float* __restrict__ rw2, const float* __restrict__ rb2,
                       float* __restrict__ out) {
    int t = threadIdx.x;  // 32 threads, t = hidden unit
    float s = rb1[t];
    for (int i = 0; i < 64; i++) s = fmaf(h[i], rw1[i * 32 + t], s);
    float z = 0.5f * s * (1.f + erff(s * 0.70710678118654752f)); // exact gelu
    float val = z * rw2[t];
#pragma unroll
    for (int o = 16; o >= 1; o >>= 1) val += __shfl_xor_sync(0xffffffffu, val, o);
    if (t == 0) out[0] = val + rb2[0];
}

// ---------------- launch ----------------------------------------------------
extern "C" void kernel_launch(void* const* d_in, const int* in_sizes, int n_in,
                              void* d_out, int out_size) {
    const float* x    = (const float*)d_in[0];
    const int*   ei   = (const int*)  d_in[1];
    const float* Wl0  = (const float*)d_in[2];
    const float* bl0  = (const float*)d_in[3];
    const float* Wr0  = (const float*)d_in[4];
    const float* br0  = (const float*)d_in[5];
    const float* att0 = (const float*)d_in[6];
    const float* bias0= (const float*)d_in[7];
    const float* Wl1  = (const float*)d_in[8];
    const float* bl1  = (const float*)d_in[9];
    const float* Wr1  = (const float*)d_in[10];
    const float* br1  = (const float*)d_in[11];
    const float* att1 = (const float*)d_in[12];
    const float* bias1= (const float*)d_in[13];
    const float* Wl2  = (const float*)d_in[14];
    const float* bl2  = (const float*)d_in[15];
    const float* Wr2  = (const float*)d_in[16];
    const float* br2  = (const float*)d_in[17];
    const float* att2 = (const float*)d_in[18];
    const float* bias2= (const float*)d_in[19];
    const float* g0   = (const float*)d_in[20];
    const float* be0  = (const float*)d_in[21];
    const float* g1   = (const float*)d_in[22];
    const float* be1  = (const float*)d_in[23];
    const float* g2   = (const float*)d_in[24];
    const float* be2  = (const float*)d_in[25];
    const float* rw1  = (const float*)d_in[26];
    const float* rb1  = (const float*)d_in[27];
    const float* rw2  = (const float*)d_in[28];
    const float* rb2  = (const float*)d_in[29];
    float* out = (float*)d_out;

    int n = in_sizes[0];           // 50000 (x is N x 1)
    int E = in_sizes[1] / 2;       // 800000
    const int* src = ei;
    const int* dst = ei + E;

    float *p_xl, *p_xr, *p_h;
    cudaGetSymbolAddress((void**)&p_xl, g_xl);
    cudaGetSymbolAddress((void**)&p_xr, g_xr);
    cudaGetSymbolAddress((void**)&p_h,  g_h);

    // CSR build (dst-sorted)
    k_init_deg<<<(n + 255) / 256, 256>>>(n);
    k_count<<<(E + 255) / 256, 256>>>(dst, E);
    k_scan<<<1, 1024>>>(n);
    k_scatter<<<(E + n + 255) / 256, 256>>>(src, dst, E, n);

    int gatBlocks = (n + 7) / 8;   // 8 warps per block of 256

    // Layer 0: rank-1 algebraic form, H=4, C=64 (no projection materialization)
    k_gat0<<<gatBlocks, 256>>>(x, Wl0, bl0, Wr0, br0, att0, bias0, g0, be0, p_h, n);

    // Layer 1: 256x256 dual projections in one launch, then GAT
    {
        dim3 grid((n + 127) / 128, 4);
        sgemm_dual<128, 8><<<grid, 256>>>(p_h, Wl1, bl1, p_xl, Wr1, br1, p_xr,
                                          n, 256, 256, 2);
    }
    k_gatG<4, 64><<<gatBlocks, 256>>>(p_xl, p_xr, att1, bias1, g1, be1, p_h, n);

    // Layer 2: 256x64 dual projections in one launch, then GAT (H=1)
    {
        dim3 grid((n + 127) / 128, 2);
        sgemm_dual<64, 4><<<grid, 256>>>(p_h, Wl2, bl2, p_xl, Wr2, br2, p_xr,
                                         n, 64, 256, 1);
    }
    k_gatG<1, 64><<<gatBlocks, 256>>>(p_xl, p_xr, att2, bias2, g2, be2, p_h, n);

    // Head on node 0
    k_head<<<1, 32>>>(p_h, rw1, rb1, rw2, rb2, out);
}